// round 16
// baseline (speedup 1.0000x reference)
#include <cuda_runtime.h>
#include <cstdint>
#include <cstddef>

#define Bn 128
#define Tn 1024
#define Dn 48
#define Hn 256
#define NBLK 128
#define NTHR 256

typedef unsigned long long ull;

// ---------------- device scratch (no allocations allowed) ----------------
__device__ float g_xT[Tn * Dn * Bn];                  // [t][48][b]
__device__ float g_o0[(size_t)Tn * 2 * Hn * Bn];      // [t][512][b]  layer0 outputs
__device__ float g_gx0[(size_t)Tn * 1024 * Bn];       // x-projection, dir 0 (incl. both biases)
__device__ float g_gx1[(size_t)Tn * 1024 * Bn];       // x-projection, dir 1
__device__ float g_h[2][2][8][16 * Hn];               // [parity][dir][bg][b*256 + j]  (b-major!)
__device__ unsigned g_cntg[16];
__device__ unsigned g_relg[16];

// ---------------- packed f32x2 helpers ----------------
__device__ __forceinline__ void ffma2(ull& d, ull a, ull b) {
    asm("fma.rn.f32x2 %0, %1, %2, %0;" : "+l"(d) : "l"(a), "l"(b));
}
__device__ __forceinline__ void fadd2(ull& d, ull a) {
    asm("add.rn.f32x2 %0, %0, %1;" : "+l"(d) : "l"(a));
}
__device__ __forceinline__ ull pack2(float a) {
    ull r;
    asm("mov.b64 %0, {%1, %1};" : "=l"(r) : "f"(a));
    return r;
}
__device__ __forceinline__ void unpack2(ull v, float& lo, float& hi) {
    asm("mov.b64 {%0, %1}, %2;" : "=f"(lo), "=f"(hi) : "l"(v));
}

// ---------------- cp.async helpers ----------------
__device__ __forceinline__ void cp_async16(void* smem_dst, const void* gsrc) {
    unsigned dst = (unsigned)__cvta_generic_to_shared(smem_dst);
    asm volatile("cp.async.cg.shared.global [%0], [%1], 16;" :: "r"(dst), "l"(gsrc) : "memory");
}
__device__ __forceinline__ void cp_commit() { asm volatile("cp.async.commit_group;" ::: "memory"); }
template<int N>
__device__ __forceinline__ void cp_wait() {
    asm volatile("cp.async.wait_group %0;" :: "n"(N) : "memory");
}

// ---------------- acquire/release atomics ----------------
__device__ __forceinline__ unsigned atom_add_acqrel(unsigned* p, unsigned v) {
    unsigned old;
    asm volatile("atom.acq_rel.gpu.add.u32 %0, [%1], %2;"
                 : "=r"(old) : "l"(p), "r"(v) : "memory");
    return old;
}
__device__ __forceinline__ void st_relaxed(unsigned* p, unsigned v) {
    asm volatile("st.relaxed.gpu.u32 [%0], %1;" :: "l"(p), "r"(v) : "memory");
}
__device__ __forceinline__ void st_release(unsigned* p, unsigned v) {
    asm volatile("st.release.gpu.u32 [%0], %1;" :: "l"(p), "r"(v) : "memory");
}
__device__ __forceinline__ unsigned ld_acquire(unsigned* p) {
    unsigned v;
    asm volatile("ld.acquire.gpu.u32 %0, [%1];" : "=r"(v) : "l"(p) : "memory");
    return v;
}

// ---------------- group barrier (8 blocks; replay-safe monotonic release) ----------------
__device__ __forceinline__ void gbar_grp(int grp, unsigned& r_last) {
    __syncthreads();
    if (threadIdx.x == 0) {
        unsigned arrived = atom_add_acqrel(&g_cntg[grp], 1);
        if (arrived == 7) {
            st_relaxed(&g_cntg[grp], 0);
            st_release(&g_relg[grp], r_last + 1);
            r_last = r_last + 1;
        } else {
            unsigned cur;
            do { cur = ld_acquire(&g_relg[grp]); } while (cur == r_last);
            r_last = cur;
        }
    }
    __syncthreads();
}

// ---------------- transpose x ----------------
__global__ void transpose_x_kernel(const float* __restrict__ x) {
    int idx = blockIdx.x * blockDim.x + threadIdx.x;
    if (idx >= Tn * Dn * Bn) return;
    int b = idx & (Bn - 1);
    int rem = idx >> 7;
    int d = rem % Dn;
    int t = rem / Dn;
    g_xT[idx] = x[((size_t)b * Tn + t) * Dn + d];
}

__device__ __forceinline__ float sigmoidf_(float v) { return 1.0f / (1.0f + __expf(-v)); }

// ================= x-projection GEMM (r14-proven: conflict-free padded s_x) =================
#define XP_SW_STRIDE 132
#define XP_XPAD(CH) ((CH) * 16 + 4)
template<int K, int CHUNK, bool SRC_O0>
__global__ void __launch_bounds__(128) xproj_kernel(
    const float* __restrict__ Wf, const float* __restrict__ Wb,
    const float* __restrict__ bihf, const float* __restrict__ bhhf,
    const float* __restrict__ bihb, const float* __restrict__ bhhb)
{
    __shared__ float s_x[8 * XP_XPAD(CHUNK)];
    __shared__ float s_w[CHUNK * XP_SW_STRIDE];

    const float* xin = SRC_O0 ? g_o0 : g_xT;     // device-side symbol resolution (ATS bug fix)

    const int t   = blockIdx.x;
    const int rt  = blockIdx.y;
    const int dir = blockIdx.z;
    const int tid = threadIdx.x;
    const int rg  = tid >> 3;              // 0..15, 8 rows each
    const int bgp = tid & 7;               // 0..7, 16 batches each

    const float* W   = dir ? Wb   : Wf;
    const float* bih = dir ? bihb : bihf;
    const float* bhh = dir ? bhhb : bhhf;
    float* gout = dir ? g_gx1 : g_gx0;

    ull acc[8][8];
#pragma unroll
    for (int u = 0; u < 8; ++u)
#pragma unroll
        for (int p = 0; p < 8; ++p) acc[u][p] = 0ull;

    const int wrow = rt * 128 + tid;
    for (int kc = 0; kc < K; kc += CHUNK) {
        const float* xsrc = xin + ((size_t)t * K + kc) * Bn;
        for (int i = tid; i < CHUNK * 32; i += 128) {
            int kk = i >> 5;
            int b4 = (i & 31) * 4;
            float4 v = *(const float4*)(xsrc + kk * Bn + b4);
            *(float4*)(s_x + (b4 >> 4) * XP_XPAD(CHUNK) + kk * 16 + (b4 & 15)) = v;
        }
        {
            const float* wsrc = W + (size_t)wrow * K + kc;
#pragma unroll
            for (int k4 = 0; k4 < CHUNK / 4; ++k4) {
                float4 v = *(const float4*)(wsrc + k4 * 4);
                s_w[(k4 * 4 + 0) * XP_SW_STRIDE + tid] = v.x;
                s_w[(k4 * 4 + 1) * XP_SW_STRIDE + tid] = v.y;
                s_w[(k4 * 4 + 2) * XP_SW_STRIDE + tid] = v.z;
                s_w[(k4 * 4 + 3) * XP_SW_STRIDE + tid] = v.w;
            }
        }
        __syncthreads();

#pragma unroll 2
        for (int kk = 0; kk < CHUNK; ++kk) {
            float4 wa = *(const float4*)(s_w + kk * XP_SW_STRIDE + rg * 8);
            float4 wb = *(const float4*)(s_w + kk * XP_SW_STRIDE + rg * 8 + 4);
            ull w0 = pack2(wa.x), w1 = pack2(wa.y), w2 = pack2(wa.z), w3 = pack2(wa.w);
            ull w4 = pack2(wb.x), w5 = pack2(wb.y), w6 = pack2(wb.z), w7 = pack2(wb.w);
            const float* xp = s_x + bgp * XP_XPAD(CHUNK) + kk * 16;
            ulonglong2 x0 = *(const ulonglong2*)(xp);
            ulonglong2 x1 = *(const ulonglong2*)(xp + 4);
            ulonglong2 x2 = *(const ulonglong2*)(xp + 8);
            ulonglong2 x3 = *(const ulonglong2*)(xp + 12);
            ull xv[8] = {x0.x, x0.y, x1.x, x1.y, x2.x, x2.y, x3.x, x3.y};
#define ROW(U, WV) \
            ffma2(acc[U][0], WV, xv[0]); ffma2(acc[U][1], WV, xv[1]); \
            ffma2(acc[U][2], WV, xv[2]); ffma2(acc[U][3], WV, xv[3]); \
            ffma2(acc[U][4], WV, xv[4]); ffma2(acc[U][5], WV, xv[5]); \
            ffma2(acc[U][6], WV, xv[6]); ffma2(acc[U][7], WV, xv[7]);
            ROW(0, w0) ROW(1, w1) ROW(2, w2) ROW(3, w3)
            ROW(4, w4) ROW(5, w5) ROW(6, w6) ROW(7, w7)
#undef ROW
        }
        __syncthreads();
    }

#pragma unroll
    for (int u = 0; u < 8; ++u) {
        int grow = rt * 128 + rg * 8 + u;
        ull bb = pack2(bih[grow] + bhh[grow]);
        float* dst = gout + ((size_t)t * 1024 + grow) * Bn + bgp * 16;
#pragma unroll
        for (int p = 0; p < 8; ++p) fadd2(acc[u][p], bb);
        *(ulonglong2*)(dst)      = make_ulonglong2(acc[u][0], acc[u][1]);
        *(ulonglong2*)(dst + 4)  = make_ulonglong2(acc[u][2], acc[u][3]);
        *(ulonglong2*)(dst + 8)  = make_ulonglong2(acc[u][4], acc[u][5]);
        *(ulonglong2*)(dst + 12) = make_ulonglong2(acc[u][6], acc[u][7]);
    }
}

// ================= recurrent phase: register gates, k-lane packing =================
// 128 blocks: dir = bid>>6, bg = (bid>>3)&7 (16 batches), hs = bid&7 (32 units)
// 256 threads: u = tid>>3 (unit 0..31), p = tid&7 (batches 2p, 2p+1)
// acc[gate][batch] f32x2 with lanes = adjacent k (partial sums; summed at end).
// s_w  [u][g][k]: one LDS.128 = 4 k's of one gate's weights (no packs)
// s_hT [b][k]:    one LDS.128 = 4 k's of one batch's h      (no packs)
// Per 4-k: 6 LDS.128 + 16 FFMA2 = 22 instr (issue 44 < 64 pipe cyc per SMSP).
#define RC_WU_STRIDE 1028
#define RC_HT_STRIDE 260
#define RC_SW_FLOATS (32 * RC_WU_STRIDE)                 // 32896
#define RC_SH_OFF    RC_SW_FLOATS
#define RC_SGX_OFF   (RC_SH_OFF + 16 * RC_HT_STRIDE)     // +4160
#define RC_SMEM_FLOATS (RC_SGX_OFF + 128 * 16)           // +2048 = 39104 fl = 156,416 B

template<bool L0P>
__global__ void __launch_bounds__(NTHR, 1) rec_kernel(
    const float* __restrict__ Whhf, const float* __restrict__ Whhb,
    const int* __restrict__ lengths)
{
    extern __shared__ float sm[];
    float* s_w  = sm;
    float* s_hT = sm + RC_SH_OFF;
    float* s_gx = sm + RC_SGX_OFF;

    const int tid = threadIdx.x;
    const int dir = blockIdx.x >> 6;
    const int bg  = (blockIdx.x >> 3) & 7;
    const int hs  = blockIdx.x & 7;
    const int grp = blockIdx.x >> 3;
    const int u   = tid >> 3;          // unit 0..31
    const int p   = tid & 7;           // batch pair

    const float* Whh = dir ? Whhb : Whhf;
    const float* gxb = dir ? g_gx1 : g_gx0;

    // ---- stage Whh slice, permuted: s_w[(r&31)*1028 + (r>>5)*256 + k] ----
    for (int i = tid; i < 128 * 64; i += NTHR) {
        int r  = i & 127;                       // gate = r>>5, unit = r&31
        int k4 = (i >> 7) * 4;
        int grow = (r >> 5) * Hn + hs * 32 + (r & 31);
        float4 v = *(const float4*)(Whh + (size_t)grow * Hn + k4);
        *(float4*)(s_w + (r & 31) * RC_WU_STRIDE + (r >> 5) * 256 + k4) = v;
    }

    // ---- zero own g_h cells, both parities (b-major layout) ----
#pragma unroll
    for (int i = 0; i < 2; ++i) {
        int c = tid + i * NTHR;                 // b = c>>5, j-local = c&31
        int off = (c >> 5) * Hn + hs * 32 + (c & 31);
        __stcg(&g_h[0][dir][bg][off], 0.0f);
        __stcg(&g_h[1][dir][bg][off], 0.0f);
    }

    float c0 = 0.f, c1 = 0.f, h0 = 0.f, h1 = 0.f;
    const int len0 = lengths[bg * 16 + 2 * p];
    const int len1 = lengths[bg * 16 + 2 * p + 1];

    unsigned r_last = ld_acquire(&g_relg[grp]);

    // ---- prefetch gx for step 0 (r14 layout/code) ----
    {
        int t0 = dir ? (Tn - 1) : 0;
        const float* gxrow = gxb + (size_t)t0 * 1024 * Bn;
        for (int i = tid; i < 512; i += NTHR) {
            int r = i >> 2, b4 = (i & 3) * 4;
            int grow = (r >> 5) * Hn + hs * 32 + (r & 31);
            cp_async16(s_gx + r * 16 + b4, gxrow + (size_t)grow * Bn + bg * 16 + b4);
        }
        cp_commit();
    }

    gbar_grp(grp, r_last);

    const int hb = tid >> 4;            // staging: h row 0..15
    const int ho = (tid & 15) * 4;      // staging: 16B offset in quarter

    for (int s = 0; s < Tn; ++s) {
        const int t = dir ? (Tn - 1 - s) : s;

        // ---- stage h in 4 k-quarters (1 KB each per... 4 KB block-wide), 4 groups ----
        {
            const float* hsrc = &g_h[s & 1][dir][bg][0];
#pragma unroll
            for (int q = 0; q < 4; ++q) {
                cp_async16(s_hT + hb * RC_HT_STRIDE + q * 64 + ho,
                           hsrc + hb * Hn + q * 64 + ho);
                cp_commit();
            }
        }

        ull ai[2] = {0ull, 0ull}, af[2] = {0ull, 0ull};
        ull ag[2] = {0ull, 0ull}, ao[2] = {0ull, 0ull};

        const float* wqb = s_w + u * RC_WU_STRIDE;
        const float* hq0 = s_hT + (2 * p) * RC_HT_STRIDE;
        const float* hq1 = hq0 + RC_HT_STRIDE;

#define QUARTER(Q, WAITN)                                                    \
        {                                                                    \
            cp_wait<WAITN>();                                                \
            __syncthreads();                                                 \
            _Pragma("unroll 2")                                              \
            for (int k4 = Q * 64; k4 < Q * 64 + 64; k4 += 4) {               \
                ulonglong2 wi = *(const ulonglong2*)(wqb + 0 * 256 + k4);    \
                ulonglong2 wf = *(const ulonglong2*)(wqb + 1 * 256 + k4);    \
                ulonglong2 wg = *(const ulonglong2*)(wqb + 2 * 256 + k4);    \
                ulonglong2 wo = *(const ulonglong2*)(wqb + 3 * 256 + k4);    \
                ulonglong2 hv0 = *(const ulonglong2*)(hq0 + k4);             \
                ulonglong2 hv1 = *(const ulonglong2*)(hq1 + k4);             \
                ffma2(ai[0], wi.x, hv0.x); ffma2(af[0], wf.x, hv0.x);        \
                ffma2(ag[0], wg.x, hv0.x); ffma2(ao[0], wo.x, hv0.x);        \
                ffma2(ai[1], wi.x, hv1.x); ffma2(af[1], wf.x, hv1.x);        \
                ffma2(ag[1], wg.x, hv1.x); ffma2(ao[1], wo.x, hv1.x);        \
                ffma2(ai[0], wi.y, hv0.y); ffma2(af[0], wf.y, hv0.y);        \
                ffma2(ag[0], wg.y, hv0.y); ffma2(ao[0], wo.y, hv0.y);        \
                ffma2(ai[1], wi.y, hv1.y); ffma2(af[1], wf.y, hv1.y);        \
                ffma2(ag[1], wg.y, hv1.y); ffma2(ao[1], wo.y, hv1.y);        \
            }                                                                \
        }
        QUARTER(0, 3)
        QUARTER(1, 2)
        QUARTER(2, 1)
        QUARTER(3, 0)
#undef QUARTER

        // ---- pointwise: cells (u, 2p), (u, 2p+1); lane-sum + gx here ----
        {
            int b0i = 2 * p, b1i = 2 * p + 1;
            float lo, hi;
            unpack2(ai[0], lo, hi); float vi0 = lo + hi + s_gx[(u)      * 16 + b0i];
            unpack2(af[0], lo, hi); float vf0 = lo + hi + s_gx[(32 + u) * 16 + b0i];
            unpack2(ag[0], lo, hi); float vg0 = lo + hi + s_gx[(64 + u) * 16 + b0i];
            unpack2(ao[0], lo, hi); float vo0 = lo + hi + s_gx[(96 + u) * 16 + b0i];
            unpack2(ai[1], lo, hi); float vi1 = lo + hi + s_gx[(u)      * 16 + b1i];
            unpack2(af[1], lo, hi); float vf1 = lo + hi + s_gx[(32 + u) * 16 + b1i];
            unpack2(ag[1], lo, hi); float vg1 = lo + hi + s_gx[(64 + u) * 16 + b1i];
            unpack2(ao[1], lo, hi); float vo1 = lo + hi + s_gx[(96 + u) * 16 + b1i];

            float ig0 = sigmoidf_(vi0), fg0 = sigmoidf_(vf0);
            float gg0 = tanhf(vg0),     og0 = sigmoidf_(vo0);
            float ig1 = sigmoidf_(vi1), fg1 = sigmoidf_(vf1);
            float gg1 = tanhf(vg1),     og1 = sigmoidf_(vo1);

            float cn0 = fg0 * c0 + ig0 * gg0;
            float hn0 = og0 * tanhf(cn0);
            float cn1 = fg1 * c1 + ig1 * gg1;
            float hn1 = og1 * tanhf(cn1);
            bool m0 = (t < len0), m1 = (t < len1);
            c0 = m0 ? cn0 : c0;  h0 = m0 ? hn0 : h0;
            c1 = m1 ? cn1 : c1;  h1 = m1 ? hn1 : h1;

            float* hw = &g_h[(s + 1) & 1][dir][bg][0];
            __stcg(&hw[b0i * Hn + hs * 32 + u], h0);
            __stcg(&hw[b1i * Hn + hs * 32 + u], h1);
            if (L0P) {
                float2 ov = make_float2(m0 ? hn0 : 0.0f, m1 ? hn1 : 0.0f);
                __stcg((float2*)&g_o0[((size_t)t * 512 + dir * Hn + hs * 32 + u) * Bn
                                      + bg * 16 + 2 * p], ov);
            }
        }

        // guard s_gx reads before prefetch overwrites it
        __syncthreads();

        // ---- prefetch gx for step s+1 (overlaps barrier spin) ----
        if (s + 1 < Tn) {
            int tn = dir ? (Tn - 2 - s) : (s + 1);
            const float* gxrow = gxb + (size_t)tn * 1024 * Bn;
            for (int i = tid; i < 512; i += NTHR) {
                int r = i >> 2, b4 = (i & 3) * 4;
                int grow = (r >> 5) * Hn + hs * 32 + (r & 31);
                cp_async16(s_gx + r * 16 + b4, gxrow + (size_t)grow * Bn + bg * 16 + b4);
            }
            cp_commit();
        }

        gbar_grp(grp, r_last);
    }
}

// ---------------- FC head ----------------
__global__ void head_kernel(const float* __restrict__ fc1_w, const float* __restrict__ fc1_b,
                            const float* __restrict__ fc2_w, const float* __restrict__ fc2_b,
                            float* __restrict__ out)
{
    __shared__ float s_h[2 * Hn];
    __shared__ float s_r[256];
    int b = blockIdx.x;
    int tid = threadIdx.x;
    int bg = b >> 4, bl = b & 15;
    // final L1 states: 1024 steps -> parity 0; g_h is [b*256 + j]
    for (int k = tid; k < 2 * Hn; k += 256) {
        int d = k >> 8;
        int j = k & (Hn - 1);
        s_h[k] = g_h[0][d][bg][bl * Hn + j];
    }
    __syncthreads();

    const float* wr = fc1_w + (size_t)tid * 2 * Hn;
    float sum = fc1_b[tid];
#pragma unroll 8
    for (int k = 0; k < 2 * Hn; ++k) sum += wr[k] * s_h[k];
    s_r[tid] = fmaxf(sum, 0.0f) * fc2_w[tid];
    __syncthreads();
    for (int st = 128; st > 0; st >>= 1) {
        if (tid < st) s_r[tid] += s_r[tid + st];
        __syncthreads();
    }
    if (tid == 0) out[b] = s_r[0] + fc2_b[0];
}

// ---------------- launch ----------------
extern "C" void kernel_launch(void* const* d_in, const int* in_sizes, int n_in,
                              void* d_out, int out_size)
{
    const float* x        = (const float*)d_in[0];
    const int*   lengths  = (const int*)  d_in[1];
    const float* w_ih_l0f = (const float*)d_in[2];
    const float* w_hh_l0f = (const float*)d_in[3];
    const float* b_ih_l0f = (const float*)d_in[4];
    const float* b_hh_l0f = (const float*)d_in[5];
    const float* w_ih_l0b = (const float*)d_in[6];
    const float* w_hh_l0b = (const float*)d_in[7];
    const float* b_ih_l0b = (const float*)d_in[8];
    const float* b_hh_l0b = (const float*)d_in[9];
    const float* w_ih_l1f = (const float*)d_in[10];
    const float* w_hh_l1f = (const float*)d_in[11];
    const float* b_ih_l1f = (const float*)d_in[12];
    const float* b_hh_l1f = (const float*)d_in[13];
    const float* w_ih_l1b = (const float*)d_in[14];
    const float* w_hh_l1b = (const float*)d_in[15];
    const float* b_ih_l1b = (const float*)d_in[16];
    const float* b_hh_l1b = (const float*)d_in[17];
    const float* fc1_w    = (const float*)d_in[18];
    const float* fc1_b    = (const float*)d_in[19];
    const float* fc2_w    = (const float*)d_in[20];
    const float* fc2_b    = (const float*)d_in[21];

    const int rec_smem = RC_SMEM_FLOATS * (int)sizeof(float);   // 156,416 B

    cudaFuncSetAttribute((const void*)rec_kernel<true>,
                         cudaFuncAttributeMaxDynamicSharedMemorySize, rec_smem);
    cudaFuncSetAttribute((const void*)rec_kernel<false>,
                         cudaFuncAttributeMaxDynamicSharedMemorySize, rec_smem);

    transpose_x_kernel<<<(Tn * Dn * Bn + 255) / 256, 256>>>(x);

    dim3 xpgrid(Tn, 8, 2);

    // layer-0 x-projection: g_xT -> g_gx
    xproj_kernel<48, 16, false><<<xpgrid, 128>>>(
        w_ih_l0f, w_ih_l0b, b_ih_l0f, b_hh_l0f, b_ih_l0b, b_hh_l0b);

    // layer-0 recurrence (h-only, consumes gx, writes g_o0)
    rec_kernel<true><<<NBLK, NTHR, rec_smem>>>(w_hh_l0f, w_hh_l0b, lengths);

    // layer-1 x-projection: g_o0 -> g_gx
    xproj_kernel<512, 32, true><<<xpgrid, 128>>>(
        w_ih_l1f, w_ih_l1b, b_ih_l1f, b_hh_l1f, b_ih_l1b, b_hh_l1b);

    // layer-1 recurrence (h-only, consumes gx)
    rec_kernel<false><<<NBLK, NTHR, rec_smem>>>(w_hh_l1f, w_hh_l1b, lengths);

    head_kernel<<<Bn, 256>>>(fc1_w, fc1_b, fc2_w, fc2_b, (float*)d_out);
}

// round 17
// speedup vs baseline: 1.4667x; 1.4667x over previous
#include <cuda_runtime.h>
#include <cstdint>
#include <cstddef>

#define Bn 128
#define Tn 1024
#define Dn 48
#define Hn 256
#define NBLK 128
#define NTHR 256

typedef unsigned long long ull;

// ---------------- device scratch (no allocations allowed) ----------------
__device__ float g_xT[Tn * Dn * Bn];                  // [t][48][b]
__device__ float g_o0[(size_t)Tn * 2 * Hn * Bn];      // [t][512][b]  layer0 outputs
__device__ float g_gx0[(size_t)Tn * 1024 * Bn];       // x-projection, dir 0 (incl. both biases)
__device__ float g_gx1[(size_t)Tn * 1024 * Bn];       // x-projection, dir 1
__device__ float g_wT0[2][48 * 1024];                 // W_ih L0 transposed: [dir][k][row]
__device__ float g_wT1[2][(size_t)512 * 1024];        // W_ih L1 transposed: [dir][k][row]
__device__ float g_h[2][2][8][Hn * 16];               // [parity][dir][bg][k*16 + b]
__device__ unsigned g_cntg[16];
__device__ unsigned g_relg[16];

// ---------------- packed f32x2 helpers ----------------
__device__ __forceinline__ void ffma2(ull& d, ull a, ull b) {
    asm("fma.rn.f32x2 %0, %1, %2, %0;" : "+l"(d) : "l"(a), "l"(b));
}
__device__ __forceinline__ void fadd2(ull& d, ull a) {
    asm("add.rn.f32x2 %0, %0, %1;" : "+l"(d) : "l"(a));
}
__device__ __forceinline__ ull pack2(float a) {
    ull r;
    asm("mov.b64 %0, {%1, %1};" : "=l"(r) : "f"(a));
    return r;
}

// ---------------- cp.async helpers ----------------
__device__ __forceinline__ void cp_async16(void* smem_dst, const void* gsrc) {
    unsigned dst = (unsigned)__cvta_generic_to_shared(smem_dst);
    asm volatile("cp.async.cg.shared.global [%0], [%1], 16;" :: "r"(dst), "l"(gsrc) : "memory");
}
__device__ __forceinline__ void cp_commit() { asm volatile("cp.async.commit_group;" ::: "memory"); }
__device__ __forceinline__ void cp_wait0()  { asm volatile("cp.async.wait_group 0;"  ::: "memory"); }
__device__ __forceinline__ void cp_wait1()  { asm volatile("cp.async.wait_group 1;"  ::: "memory"); }

// ---------------- acquire/release atomics ----------------
__device__ __forceinline__ unsigned atom_add_acqrel(unsigned* p, unsigned v) {
    unsigned old;
    asm volatile("atom.acq_rel.gpu.add.u32 %0, [%1], %2;"
                 : "=r"(old) : "l"(p), "r"(v) : "memory");
    return old;
}
__device__ __forceinline__ void st_relaxed(unsigned* p, unsigned v) {
    asm volatile("st.relaxed.gpu.u32 [%0], %1;" :: "l"(p), "r"(v) : "memory");
}
__device__ __forceinline__ void st_release(unsigned* p, unsigned v) {
    asm volatile("st.release.gpu.u32 [%0], %1;" :: "l"(p), "r"(v) : "memory");
}
__device__ __forceinline__ unsigned ld_acquire(unsigned* p) {
    unsigned v;
    asm volatile("ld.acquire.gpu.u32 %0, [%1];" : "=r"(v) : "l"(p) : "memory");
    return v;
}

// ---------------- group barrier (8 blocks; replay-safe monotonic release) ----------------
__device__ __forceinline__ void gbar_grp(int grp, unsigned& r_last) {
    __syncthreads();
    if (threadIdx.x == 0) {
        unsigned arrived = atom_add_acqrel(&g_cntg[grp], 1);
        if (arrived == 7) {
            st_relaxed(&g_cntg[grp], 0);
            st_release(&g_relg[grp], r_last + 1);
            r_last = r_last + 1;
        } else {
            unsigned cur;
            do { cur = ld_acquire(&g_relg[grp]); } while (cur == r_last);
            r_last = cur;
        }
    }
    __syncthreads();
}

// ---------------- transpose x ----------------
__global__ void transpose_x_kernel(const float* __restrict__ x) {
    int idx = blockIdx.x * blockDim.x + threadIdx.x;
    if (idx >= Tn * Dn * Bn) return;
    int b = idx & (Bn - 1);
    int rem = idx >> 7;
    int d = rem % Dn;
    int t = rem / Dn;
    g_xT[idx] = x[((size_t)b * Tn + t) * Dn + d];
}

// ---------------- transpose W_ih: [row][K] -> [k][1024] (one-time prep) ----------------
template<int K, bool L1SEL>
__global__ void wtrans_kernel(const float* __restrict__ Wf, const float* __restrict__ Wb) {
    int idx = blockIdx.x * blockDim.x + threadIdx.x;
    if (idx >= 2 * K * 1024) return;
    int dir = idx / (K * 1024);
    int rem = idx - dir * (K * 1024);
    int row = rem / K;
    int k   = rem - row * K;
    const float* W = dir ? Wb : Wf;
    float v = W[(size_t)row * K + k];
    if (L1SEL) g_wT1[dir][(size_t)k * 1024 + row] = v;
    else       g_wT0[dir][(size_t)k * 1024 + row] = v;
}

__device__ __forceinline__ float sigmoidf_(float v) { return 1.0f / (1.0f + __expf(-v)); }

// ================= x-projection GEMM: double-buffered cp.async pipeline =================
// 128 threads, thread = 8 rows x 16 batch (r14-proven compute loop, bit-identical).
// Staging is fully async: x and pre-transposed w stream into buffer (c+1)&1 via
// cp.async while chunk c is computed — no LDG-latency exposure, no transpose ALU.
#define XP_SW_STRIDE 132
#define XP_XPAD(CH) ((CH) * 16 + 4)
template<int K, int CHUNK, bool SRC_O0>
__global__ void __launch_bounds__(128) xproj_kernel(
    const float* __restrict__ bihf, const float* __restrict__ bhhf,
    const float* __restrict__ bihb, const float* __restrict__ bhhb)
{
    extern __shared__ float sm[];
    float* s_x = sm;                                   // [2][8][XP_XPAD]
    float* s_w = sm + 2 * 8 * XP_XPAD(CHUNK);          // [2][CHUNK][132]

    const float* xin = SRC_O0 ? g_o0 : g_xT;           // device-side symbol resolution
    constexpr int NC = K / CHUNK;

    const int t   = blockIdx.x;
    const int rt  = blockIdx.y;
    const int dir = blockIdx.z;
    const int tid = threadIdx.x;
    const int rg  = tid >> 3;              // 0..15, 8 rows each
    const int bgp = tid & 7;               // 0..7, 16 batches each

    const float* wT  = SRC_O0 ? g_wT1[dir] : g_wT0[dir];
    const float* bih = dir ? bihb : bihf;
    const float* bhh = dir ? bhhb : bhhf;
    float* gout = dir ? g_gx1 : g_gx0;

    ull acc[8][8];
#pragma unroll
    for (int u = 0; u < 8; ++u)
#pragma unroll
        for (int p = 0; p < 8; ++p) acc[u][p] = 0ull;

    // stage chunk c into buffer bsel (x: padded per-bgp layout; w: [kk][132] rows)
    auto stage = [&](int c, int bsel) {
        const float* xsrc = xin + ((size_t)t * K + c * CHUNK) * Bn;
        float* xb = s_x + bsel * 8 * XP_XPAD(CHUNK);
        for (int i = tid; i < CHUNK * 32; i += 128) {
            int kk = i >> 5;
            int b4 = (i & 31) * 4;
            cp_async16(xb + (b4 >> 4) * XP_XPAD(CHUNK) + kk * 16 + (b4 & 15),
                       xsrc + kk * Bn + b4);
        }
        const float* wsrc = wT + (size_t)(c * CHUNK) * 1024 + rt * 128;
        float* wb = s_w + bsel * CHUNK * XP_SW_STRIDE;
        for (int i = tid; i < CHUNK * 32; i += 128) {
            int kk = i >> 5;
            int f4 = (i & 31) * 4;
            cp_async16(wb + kk * XP_SW_STRIDE + f4, wsrc + (size_t)kk * 1024 + f4);
        }
    };

    stage(0, 0);
    cp_commit();

    for (int c = 0; c < NC; ++c) {
        if (c + 1 < NC) {
            stage(c + 1, (c + 1) & 1);
            cp_commit();
            cp_wait1();
        } else {
            cp_wait0();
        }
        __syncthreads();

        const float* xb = s_x + (c & 1) * 8 * XP_XPAD(CHUNK);
        const float* wb = s_w + (c & 1) * CHUNK * XP_SW_STRIDE;

#pragma unroll 2
        for (int kk = 0; kk < CHUNK; ++kk) {
            float4 wa = *(const float4*)(wb + kk * XP_SW_STRIDE + rg * 8);
            float4 wc = *(const float4*)(wb + kk * XP_SW_STRIDE + rg * 8 + 4);
            ull w0 = pack2(wa.x), w1 = pack2(wa.y), w2 = pack2(wa.z), w3 = pack2(wa.w);
            ull w4 = pack2(wc.x), w5 = pack2(wc.y), w6 = pack2(wc.z), w7 = pack2(wc.w);
            const float* xp = xb + bgp * XP_XPAD(CHUNK) + kk * 16;
            ulonglong2 x0 = *(const ulonglong2*)(xp);
            ulonglong2 x1 = *(const ulonglong2*)(xp + 4);
            ulonglong2 x2 = *(const ulonglong2*)(xp + 8);
            ulonglong2 x3 = *(const ulonglong2*)(xp + 12);
            ull xv[8] = {x0.x, x0.y, x1.x, x1.y, x2.x, x2.y, x3.x, x3.y};
#define ROW(U, WV) \
            ffma2(acc[U][0], WV, xv[0]); ffma2(acc[U][1], WV, xv[1]); \
            ffma2(acc[U][2], WV, xv[2]); ffma2(acc[U][3], WV, xv[3]); \
            ffma2(acc[U][4], WV, xv[4]); ffma2(acc[U][5], WV, xv[5]); \
            ffma2(acc[U][6], WV, xv[6]); ffma2(acc[U][7], WV, xv[7]);
            ROW(0, w0) ROW(1, w1) ROW(2, w2) ROW(3, w3)
            ROW(4, w4) ROW(5, w5) ROW(6, w6) ROW(7, w7)
#undef ROW
        }
        __syncthreads();
    }

#pragma unroll
    for (int u = 0; u < 8; ++u) {
        int grow = rt * 128 + rg * 8 + u;
        ull bb = pack2(bih[grow] + bhh[grow]);
        float* dst = gout + ((size_t)t * 1024 + grow) * Bn + bgp * 16;
#pragma unroll
        for (int p = 0; p < 8; ++p) fadd2(acc[u][p], bb);
        *(ulonglong2*)(dst)      = make_ulonglong2(acc[u][0], acc[u][1]);
        *(ulonglong2*)(dst + 4)  = make_ulonglong2(acc[u][2], acc[u][3]);
        *(ulonglong2*)(dst + 8)  = make_ulonglong2(acc[u][4], acc[u][5]);
        *(ulonglong2*)(dst + 12) = make_ulonglong2(acc[u][6], acc[u][7]);
    }
}

// ================= recurrent phase (r14-proven, verbatim) =================
#define RC_SW_STRIDE 132
#define RC_SW_FLOATS (256 * RC_SW_STRIDE)       // 33792
#define RC_SH_OFF    RC_SW_FLOATS
#define RC_SGX_OFF   (RC_SH_OFF + 4096)
#define RC_SPART_OFF (RC_SGX_OFF + 2048)
#define RC_SG_OFF    (RC_SPART_OFF + 8192)
#define RC_SMEM_FLOATS (RC_SG_OFF + 2048)       // 50176 floats = 200704 B

template<bool L0P>
__global__ void __launch_bounds__(NTHR, 1) rec_kernel(
    const float* __restrict__ Whhf, const float* __restrict__ Whhb,
    const int* __restrict__ lengths)
{
    extern __shared__ float sm[];
    float* s_w    = sm;
    float* s_h    = sm + RC_SH_OFF;
    float* s_gx   = sm + RC_SGX_OFF;
    float* s_part = sm + RC_SPART_OFF;
    float* s_g    = sm + RC_SG_OFF;

    const int tid = threadIdx.x;
    const int dir = blockIdx.x >> 6;
    const int bg  = (blockIdx.x >> 3) & 7;
    const int hs  = blockIdx.x & 7;
    const int grp = blockIdx.x >> 3;
    const int kg  = tid >> 6;
    const int lid = tid & 63;
    const int rg  = lid >> 2;          // 0..15, 8 gate-rows each
    const int bq  = lid & 3;           // 0..3

    const float* Whh = dir ? Whhb : Whhf;
    const float* gxb = dir ? g_gx1 : g_gx0;

    // ---- stage Whh slice: s_w[k][r] = Whh[grow(r)][k] ----
    for (int i = tid; i < 128 * 64; i += NTHR) {
        int r  = i >> 6;
        int k4 = (i & 63) * 4;
        int grow = (r >> 5) * Hn + hs * 32 + (r & 31);
        float4 v = *(const float4*)(Whh + (size_t)grow * Hn + k4);
        s_w[(k4 + 0) * RC_SW_STRIDE + r] = v.x;
        s_w[(k4 + 1) * RC_SW_STRIDE + r] = v.y;
        s_w[(k4 + 2) * RC_SW_STRIDE + r] = v.z;
        s_w[(k4 + 3) * RC_SW_STRIDE + r] = v.w;
    }

    // ---- zero own g_h slice, both parities ----
#pragma unroll
    for (int i = 0; i < 2; ++i) {
        int c = tid + i * NTHR;
        __stcg(&g_h[0][dir][bg][hs * 512 + c], 0.0f);
        __stcg(&g_h[1][dir][bg][hs * 512 + c], 0.0f);
    }

    float c_reg[2] = {0.0f, 0.0f};
    float h_reg[2] = {0.0f, 0.0f};
    const int len = lengths[bg * 16 + (tid & 15)];

    unsigned r_last = ld_acquire(&g_relg[grp]);

    // ---- prefetch gx for step 0 ----
    {
        int t0 = dir ? (Tn - 1) : 0;
        const float* gxrow = gxb + (size_t)t0 * 1024 * Bn;
        for (int i = tid; i < 512; i += NTHR) {
            int r = i >> 2, b4 = (i & 3) * 4;
            int grow = (r >> 5) * Hn + hs * 32 + (r & 31);
            cp_async16(s_gx + r * 16 + b4, gxrow + (size_t)grow * Bn + bg * 16 + b4);
        }
        cp_commit();
    }

    gbar_grp(grp, r_last);

    for (int s = 0; s < Tn; ++s) {
        const int t = dir ? (Tn - 1 - s) : s;

        // ---- stage h [256 k][16 b] (contiguous 16 KB) ----
        {
            const float* hsrc = &g_h[s & 1][dir][bg][0];
            for (int i = tid; i < 1024; i += NTHR)
                cp_async16(s_h + i * 4, hsrc + i * 4);
            cp_commit();
        }
        cp_wait0();          // h + previously committed gx
        __syncthreads();

        // ---- gates partials over own k quarter ----
        ull acc[8][2];
#pragma unroll
        for (int u = 0; u < 8; ++u) { acc[u][0] = 0ull; acc[u][1] = 0ull; }

#pragma unroll 4
        for (int kk = 0; kk < 64; ++kk) {
            int k = kg * 64 + kk;
            float4 wa = *(const float4*)(s_w + k * RC_SW_STRIDE + rg * 8);
            float4 wb = *(const float4*)(s_w + k * RC_SW_STRIDE + rg * 8 + 4);
            ull w0 = pack2(wa.x), w1 = pack2(wa.y), w2 = pack2(wa.z), w3 = pack2(wa.w);
            ull w4 = pack2(wb.x), w5 = pack2(wb.y), w6 = pack2(wb.z), w7 = pack2(wb.w);
            ulonglong2 hp = *(const ulonglong2*)(s_h + k * 16 + bq * 4);
            ffma2(acc[0][0], w0, hp.x); ffma2(acc[0][1], w0, hp.y);
            ffma2(acc[1][0], w1, hp.x); ffma2(acc[1][1], w1, hp.y);
            ffma2(acc[2][0], w2, hp.x); ffma2(acc[2][1], w2, hp.y);
            ffma2(acc[3][0], w3, hp.x); ffma2(acc[3][1], w3, hp.y);
            ffma2(acc[4][0], w4, hp.x); ffma2(acc[4][1], w4, hp.y);
            ffma2(acc[5][0], w5, hp.x); ffma2(acc[5][1], w5, hp.y);
            ffma2(acc[6][0], w6, hp.x); ffma2(acc[6][1], w6, hp.y);
            ffma2(acc[7][0], w7, hp.x); ffma2(acc[7][1], w7, hp.y);
        }

        // ---- store partials: s_part[kg][r][b] ----
#pragma unroll
        for (int u = 0; u < 8; ++u) {
            int r = rg * 8 + u;
            *(ulonglong2*)(s_part + (size_t)(kg * 128 + r) * 16 + bq * 4) =
                make_ulonglong2(acc[u][0], acc[u][1]);
        }
        __syncthreads();

        // ---- reduce k-groups + gx (biases folded into gx) -> s_g ----
#pragma unroll
        for (int i = 0; i < 8; ++i) {
            int idx = tid + i * NTHR;
            s_g[idx] = s_gx[idx] + s_part[idx] + s_part[2048 + idx]
                     + s_part[4096 + idx] + s_part[6144 + idx];
        }
        __syncthreads();

        // ---- prefetch gx for step s+1 (independent of h/barrier) ----
        if (s + 1 < Tn) {
            int tn = dir ? (Tn - 2 - s) : (s + 1);
            const float* gxrow = gxb + (size_t)tn * 1024 * Bn;
            for (int i = tid; i < 512; i += NTHR) {
                int r = i >> 2, b4 = (i & 3) * 4;
                int grow = (r >> 5) * Hn + hs * 32 + (r & 31);
                cp_async16(s_gx + r * 16 + b4, gxrow + (size_t)grow * Bn + bg * 16 + b4);
            }
            cp_commit();
        }

        // ---- pointwise: cells tid and tid+256 ----
#pragma unroll
        for (int i = 0; i < 2; ++i) {
            int c = tid + i * NTHR;             // u = c>>4, b = c&15
            float ig = sigmoidf_(s_g[c]);
            float fg = sigmoidf_(s_g[512 + c]);
            float gg = tanhf    (s_g[1024 + c]);
            float og = sigmoidf_(s_g[1536 + c]);
            float cn = fg * c_reg[i] + ig * gg;
            float hn = og * tanhf(cn);
            bool m = (t < len);
            c_reg[i] = m ? cn : c_reg[i];
            float hw = m ? hn : h_reg[i];
            h_reg[i] = hw;
            __stcg(&g_h[(s + 1) & 1][dir][bg][hs * 512 + c], hw);
            if (L0P)
                __stcg(&g_o0[((size_t)t * 512 + dir * Hn + hs * 32 + (c >> 4)) * Bn
                             + bg * 16 + (c & 15)], m ? hn : 0.0f);
        }

        gbar_grp(grp, r_last);
    }
}

// ---------------- FC head ----------------
__global__ void head_kernel(const float* __restrict__ fc1_w, const float* __restrict__ fc1_b,
                            const float* __restrict__ fc2_w, const float* __restrict__ fc2_b,
                            float* __restrict__ out)
{
    __shared__ float s_h[2 * Hn];
    __shared__ float s_r[256];
    int b = blockIdx.x;
    int tid = threadIdx.x;
    int bg = b >> 4, bl = b & 15;
    // final L1 states: 1024 steps -> parity 0
    for (int k = tid; k < 2 * Hn; k += 256) {
        int d = k >> 8;
        int j = k & (Hn - 1);
        s_h[k] = g_h[0][d][bg][j * 16 + bl];
    }
    __syncthreads();

    const float* wr = fc1_w + (size_t)tid * 2 * Hn;
    float sum = fc1_b[tid];
#pragma unroll 8
    for (int k = 0; k < 2 * Hn; ++k) sum += wr[k] * s_h[k];
    s_r[tid] = fmaxf(sum, 0.0f) * fc2_w[tid];
    __syncthreads();
    for (int st = 128; st > 0; st >>= 1) {
        if (tid < st) s_r[tid] += s_r[tid + st];
        __syncthreads();
    }
    if (tid == 0) out[b] = s_r[0] + fc2_b[0];
}

// ---------------- launch ----------------
extern "C" void kernel_launch(void* const* d_in, const int* in_sizes, int n_in,
                              void* d_out, int out_size)
{
    const float* x        = (const float*)d_in[0];
    const int*   lengths  = (const int*)  d_in[1];
    const float* w_ih_l0f = (const float*)d_in[2];
    const float* w_hh_l0f = (const float*)d_in[3];
    const float* b_ih_l0f = (const float*)d_in[4];
    const float* b_hh_l0f = (const float*)d_in[5];
    const float* w_ih_l0b = (const float*)d_in[6];
    const float* w_hh_l0b = (const float*)d_in[7];
    const float* b_ih_l0b = (const float*)d_in[8];
    const float* b_hh_l0b = (const float*)d_in[9];
    const float* w_ih_l1f = (const float*)d_in[10];
    const float* w_hh_l1f = (const float*)d_in[11];
    const float* b_ih_l1f = (const float*)d_in[12];
    const float* b_hh_l1f = (const float*)d_in[13];
    const float* w_ih_l1b = (const float*)d_in[14];
    const float* w_hh_l1b = (const float*)d_in[15];
    const float* b_ih_l1b = (const float*)d_in[16];
    const float* b_hh_l1b = (const float*)d_in[17];
    const float* fc1_w    = (const float*)d_in[18];
    const float* fc1_b    = (const float*)d_in[19];
    const float* fc2_w    = (const float*)d_in[20];
    const float* fc2_b    = (const float*)d_in[21];

    const int rec_smem = RC_SMEM_FLOATS * (int)sizeof(float);   // 200,704 B
    const int xp0_smem = (2 * 8 * XP_XPAD(16) + 2 * 16 * XP_SW_STRIDE) * (int)sizeof(float); // 33,536
    const int xp1_smem = (2 * 8 * XP_XPAD(32) + 2 * 32 * XP_SW_STRIDE) * (int)sizeof(float); // 66,816

    cudaFuncSetAttribute((const void*)rec_kernel<true>,
                         cudaFuncAttributeMaxDynamicSharedMemorySize, rec_smem);
    cudaFuncSetAttribute((const void*)rec_kernel<false>,
                         cudaFuncAttributeMaxDynamicSharedMemorySize, rec_smem);
    cudaFuncSetAttribute((const void*)xproj_kernel<48, 16, false>,
                         cudaFuncAttributeMaxDynamicSharedMemorySize, xp0_smem);
    cudaFuncSetAttribute((const void*)xproj_kernel<512, 32, true>,
                         cudaFuncAttributeMaxDynamicSharedMemorySize, xp1_smem);

    transpose_x_kernel<<<(Tn * Dn * Bn + 255) / 256, 256>>>(x);

    // one-time weight transposes (both layers; independent of data flow)
    wtrans_kernel<48,  false><<<(2 * 48 * 1024 + 255) / 256, 256>>>(w_ih_l0f, w_ih_l0b);
    wtrans_kernel<512, true ><<<(2 * 512 * 1024 + 255) / 256, 256>>>(w_ih_l1f, w_ih_l1b);

    dim3 xpgrid(Tn, 8, 2);

    // layer-0 x-projection: g_xT -> g_gx
    xproj_kernel<48, 16, false><<<xpgrid, 128, xp0_smem>>>(
        b_ih_l0f, b_hh_l0f, b_ih_l0b, b_hh_l0b);

    // layer-0 recurrence (h-only, consumes gx, writes g_o0)
    rec_kernel<true><<<NBLK, NTHR, rec_smem>>>(w_hh_l0f, w_hh_l0b, lengths);

    // layer-1 x-projection: g_o0 -> g_gx
    xproj_kernel<512, 32, true><<<xpgrid, 128, xp1_smem>>>(
        b_ih_l1f, b_hh_l1f, b_ih_l1b, b_hh_l1b);

    // layer-1 recurrence (h-only, consumes gx)
    rec_kernel<false><<<NBLK, NTHR, rec_smem>>>(w_hh_l1f, w_hh_l1b, lengths);

    head_kernel<<<Bn, 256>>>(fc1_w, fc1_b, fc2_w, fc2_b, (float*)d_out);
}